// round 12
// baseline (speedup 1.0000x reference)
#include <cuda_runtime.h>
#include <cuda_fp16.h>
#include <math.h>
#include <stdint.h>

#define BATCH 16
#define MAXPIX (268u * 268u)

// activations NHWC fp16 (single precision-term), ping-pong
__device__ __half g_actA[16u * MAXPIX * 64u];
__device__ __half g_actB[16u * MAXPIX * 64u];
// fp16 body weights, K-MAJOR: [5][16][tap 9][ic 64][oc 64]
__device__ __half g_wt[5u * 16u * 9u * 64u * 64u];
// fp16 tail weights: [16][tap 9][ic 64][oc 8(pad)]
__device__ __half g_twt[16u * 9u * 64u * 8u];

// ---------------- helpers ----------------
__device__ __forceinline__ uint32_t smem_u32(const void* p) {
    uint32_t a;
    asm("{ .reg .u64 t; cvta.to.shared.u64 t, %1; cvt.u32.u64 %0, t; }" : "=r"(a) : "l"(p));
    return a;
}
__device__ __forceinline__ uint32_t swz(uint32_t o) { return o ^ ((o >> 3) & 0x70); }

__device__ __forceinline__ void ldsm4(uint32_t r[4], uint32_t addr) {
    asm volatile("ldmatrix.sync.aligned.m8n8.x4.shared.b16 {%0,%1,%2,%3}, [%4];"
        : "=r"(r[0]), "=r"(r[1]), "=r"(r[2]), "=r"(r[3]) : "r"(addr));
}
__device__ __forceinline__ void ldsm4t(uint32_t r[4], uint32_t addr) {
    asm volatile("ldmatrix.sync.aligned.m8n8.x4.trans.shared.b16 {%0,%1,%2,%3}, [%4];"
        : "=r"(r[0]), "=r"(r[1]), "=r"(r[2]), "=r"(r[3]) : "r"(addr));
}
__device__ __forceinline__ void mma16816(float d[4], const uint32_t a[4], uint32_t b0, uint32_t b1) {
    asm volatile("mma.sync.aligned.m16n8k16.row.col.f32.f16.f16.f32 "
        "{%0,%1,%2,%3}, {%4,%5,%6,%7}, {%8,%9}, {%0,%1,%2,%3};"
        : "+f"(d[0]), "+f"(d[1]), "+f"(d[2]), "+f"(d[3])
        : "r"(a[0]), "r"(a[1]), "r"(a[2]), "r"(a[3]), "r"(b0), "r"(b1));
}
__device__ __forceinline__ void cp16(uint32_t dst, const void* src) {
    asm volatile("cp.async.cg.shared.global [%0], [%1], 16;" :: "r"(dst), "l"(src) : "memory");
}
#define CP_COMMIT() asm volatile("cp.async.commit_group;" ::: "memory")
#define CP_WAIT(n)  asm volatile("cp.async.wait_group %0;" :: "n"(n) : "memory")

// smem layout for body kernel (24x16 px tile -> 26x18 slab = 59904B, pad 60416)
#define SM_WS   0          // 9 x 8192 = 73728
#define SM_A0   73728
#define SM_A1   134144
#define SMEM_BODY 194560

// smem layout for tail kernel (8x16 px tile, 10x18 slab)
#define TSM_WS  0          // 9 x 1024 = 9216
#define TSM_A0  9216
#define TSM_A1  32768
#define SMEM_TAIL 56320

#define NTB 384            // body threads (12 warps, 3/SMSP)
#define NTT 256            // tail threads

// ---------------- weight prep: [l][b][tap][ic][oc], cw folded, fp16 ----------
__global__ void prep_kernel(const float* __restrict__ bw, float cw) {
    int idx = blockIdx.x * blockDim.x + threadIdx.x;
    const int N = 5 * 16 * 9 * 64 * 64;
    if (idx >= N) return;
    int oc = idx & 63;
    int ic = (idx >> 6) & 63;
    int tap = (idx >> 12) % 9;
    int rest = idx / (9 * 64 * 64);   // l*16+b
    float v = bw[(((size_t)rest * 64 + oc) * 64 + ic) * 9 + tap] * cw;
    g_wt[idx] = __float2half_rn(v);
}

// tail weights: [b][tap][ic][oc8], cw folded, oc>=3 zero
__global__ void prep_tail_kernel(const float* __restrict__ tw, float cw) {
    int idx = blockIdx.x * blockDim.x + threadIdx.x;
    const int N = 16 * 9 * 64 * 8;
    if (idx >= N) return;
    int oc = idx & 7;
    int ic = (idx >> 3) & 63;
    int tap = (idx >> 9) % 9;
    int b = idx / (9 * 64 * 8);
    float v = 0.f;
    if (oc < 3) v = tw[(((size_t)b * 3 + oc) * 64 + ic) * 9 + tap] * cw;
    g_twt[idx] = __float2half_rn(v);
}

// ---------------- head (scalar fp32, 64 oc per block, writes NHWC fp16) -----
__global__ __launch_bounds__(256)
void head_kernel(const float* __restrict__ noise, const float* __restrict__ hw,
                 const float* __restrict__ hb, __half* __restrict__ oh,
                 float cw, float cb)
{
    const int Sout = 268;
    int b = blockIdx.z;
    int tx0 = blockIdx.x * 32, ty0 = blockIdx.y * 8;
    int tid = threadIdx.x, tx = tid & 31, ty = tid >> 5;

    __shared__ __align__(16) float ws[3 * 9 * 64];   // [ic][k][oc64]
    __shared__ float xs[3 * 10 * 34];

    for (int i = tid; i < 3 * 576; i += 256) {
        int oc = i & 63, k = (i >> 6) % 9, ic = i / 576;
        ws[i] = hw[((b * 64 + oc) * 3 + ic) * 9 + k];
    }
    for (int i = tid; i < 3 * 340; i += 256) {
        int ic = i / 340, rem = i % 340, r = rem / 34, c = rem % 34;
        int gy = ty0 + r - 7, gx = tx0 + c - 7;
        float v = 0.f;
        if (gy >= 0 && gy < 256 && gx >= 0 && gx < 256)
            v = noise[((size_t)(b * 3 + ic) * 256 + gy) * 256 + gx];
        xs[i] = v;
    }
    __syncthreads();

    float acc[64];
#pragma unroll
    for (int o = 0; o < 64; o++) acc[o] = 0.f;
#pragma unroll
    for (int ic = 0; ic < 3; ic++) {
        const float* xp = xs + ic * 340 + ty * 34 + tx;
        float xv[9];
#pragma unroll
        for (int ky = 0; ky < 3; ky++)
#pragma unroll
            for (int kx = 0; kx < 3; kx++) xv[ky * 3 + kx] = xp[ky * 34 + kx];
        const float4* wp = (const float4*)(ws + ic * 576);
#pragma unroll
        for (int k = 0; k < 9; k++) {
#pragma unroll
            for (int q = 0; q < 16; q++) {
                float4 w4 = wp[k * 16 + q];
                acc[q * 4 + 0] = fmaf(xv[k], w4.x, acc[q * 4 + 0]);
                acc[q * 4 + 1] = fmaf(xv[k], w4.y, acc[q * 4 + 1]);
                acc[q * 4 + 2] = fmaf(xv[k], w4.z, acc[q * 4 + 2]);
                acc[q * 4 + 3] = fmaf(xv[k], w4.w, acc[q * 4 + 3]);
            }
        }
    }

    int ox = tx0 + tx, oy = ty0 + ty;
    if (ox < Sout && oy < Sout) {
        __align__(16) __half h64[64];
#pragma unroll
        for (int o = 0; o < 64; o++) {
            float v = acc[o] * cw + hb[b * 64 + o] * cb;
            v = v > 0.f ? v : 0.02f * v;
            h64[o] = __float2half_rn(v);
        }
        size_t obase = ((size_t)b * (Sout * Sout) + (size_t)oy * Sout + ox) * 64;
        uint4* dh = (uint4*)(oh + obase);
#pragma unroll
        for (int q = 0; q < 8; q++) dh[q] = ((uint4*)h64)[q];
    }
}

// ---------------- A-slab gathers via cp.async ----------------
// body: 26 rows x 18 px slab (24x16 tile), 384-thread stride
__device__ __forceinline__ void gather26(uint32_t dst, const __half* __restrict__ src,
                                         int oy0, int ox0, int Sin, int tid)
{
    for (int i = tid; i < 3744; i += NTB) {   // 468 px x 8 chunks
        int e = i >> 3, q = i & 7;
        int er = e / 18, ec = e - er * 18;
        int iy = oy0 + er; if (iy > Sin - 1) iy = Sin - 1;
        int ix = ox0 + ec; if (ix > Sin - 1) ix = Sin - 1;
        size_t base = ((size_t)iy * Sin + ix) * 64 + q * 8;
        cp16(dst + swz((uint32_t)(e * 128 + q * 16)), src + base);
    }
    CP_COMMIT();
}
// tail: 10 rows x 18 px slab (8x16 tile), 256-thread stride
__device__ __forceinline__ void gather10(uint32_t dst, const __half* __restrict__ src,
                                         int oy0, int ox0, int Sin, int tid)
{
    for (int i = tid; i < 1440; i += NTT) {
        int e = i >> 3, q = i & 7;
        int er = e / 18, ec = e - er * 18;
        int iy = oy0 + er; if (iy > Sin - 1) iy = Sin - 1;
        int ix = ox0 + ec; if (ix > Sin - 1) ix = Sin - 1;
        size_t base = ((size_t)iy * Sin + ix) * 64 + q * 8;
        cp16(dst + swz((uint32_t)(e * 128 + q * 16)), src + base);
    }
    CP_COMMIT();
}

// ---------------- body (mma.sync fp16, 24x16 px tile, 12 warps) -------------
__global__ __launch_bounds__(NTB, 1)
void body_mma_kernel(const __half* __restrict__ in_a,
                     const __half* __restrict__ wt,     // [16][9][64 ic][64 oc]
                     const float* __restrict__ bias,    // [16][64]
                     __half* __restrict__ out_a,
                     int Sin, float cb)
{
    extern __shared__ __align__(1024) char smem[];
    const int Sout = Sin - 2;
    const int b = blockIdx.z, slot = blockIdx.x;
    const int tid = threadIdx.x, wid = tid >> 5, lane = tid & 31;
    const int wm = wid % 6, wn = wid / 6;   // 6 row-groups (4 rows each) x 2 oc-halves
    uint32_t sbase = smem_u32(smem);
    const uint32_t A[2] = { sbase + SM_A0, sbase + SM_A1 };

    // stage weights: [tap][ic 64][128B oc], SW128-swizzled
    {
        const __half* wb = wt + (size_t)b * 9 * 4096;
        for (int i = tid; i < 4608; i += NTB) {
            int j = i & 511, tap = i >> 9;
            int ic = j >> 3, q = j & 7;
            const uint4* src = (const uint4*)(wb + ((size_t)tap * 64 + ic) * 64) + q;
            *(uint4*)(smem + SM_WS + tap * 8192 + swz(ic * 128 + q * 16)) = *src;
        }
    }

    float bv[8];
#pragma unroll
    for (int j = 0; j < 4; j++) {
        int oc = wn * 32 + j * 8 + (lane & 3) * 2;
        bv[j * 2 + 0] = bias[b * 64 + oc] * cb;
        bv[j * 2 + 1] = bias[b * 64 + oc + 1] * cb;
    }

    const __half* ia = in_a + (size_t)b * Sin * Sin * 64;
    const int nrt = (Sout + 23) / 24, nct = (Sout + 15) >> 4;
    const int ntiles = nrt * nct;
    const size_t Spo = (size_t)Sout * Sout;

    const int laneA = (lane & 15) * 128 + (lane >> 4) * 16;
    const int laneB = (lane & 15) * 128 + (lane >> 4) * 16 + wn * 64;

    int s = 0;
    {
        int t0 = slot;
        if (t0 < ntiles) {
            int rt = t0 / nct, ct = t0 - rt * nct;
            gather26(A[0], ia, rt * 24, ct * 16, Sin, tid);
        } else {
            CP_COMMIT();
        }
    }

    for (int tt = slot; tt < ntiles; tt += 9) {
        int rt = tt / nct, ct = tt - rt * nct;
        int oy0 = rt * 24, ox0 = ct * 16;

        __syncthreads();
        int tn = tt + 9;
        if (tn < ntiles) {
            int rtn = tn / nct, ctn = tn - rtn * nct;
            gather26(A[s ^ 1], ia, rtn * 24, ctn * 16, Sin, tid);
        } else {
            CP_COMMIT();
        }
        CP_WAIT(1); __syncthreads();

        float acc[4][4][4];
#pragma unroll
        for (int mt = 0; mt < 4; mt++)
#pragma unroll
            for (int j = 0; j < 4; j++)
#pragma unroll
                for (int r = 0; r < 4; r++) acc[mt][j][r] = 0.f;

#pragma unroll
        for (int ky = 0; ky < 3; ky++) {
#pragma unroll
            for (int kx = 0; kx < 3; kx++) {
                uint32_t wtile = sbase + SM_WS + (ky * 3 + kx) * 8192;
#pragma unroll
                for (int kc = 0; kc < 4; kc++) {
                    uint32_t a_f[4][4];
#pragma unroll
                    for (int mt = 0; mt < 4; mt++) {
                        int ebase = ((wm * 4 + mt + ky) * 18 + kx) * 128 + kc * 32;
                        ldsm4(a_f[mt], A[s] + swz((uint32_t)(ebase + laneA)));
                    }
                    uint32_t bf[2][4];
#pragma unroll
                    for (int nt = 0; nt < 2; nt++) {
                        uint32_t off = swz((uint32_t)(kc * 2048 + laneB + nt * 32));
                        ldsm4t(bf[nt], wtile + off);
                    }
#pragma unroll
                    for (int mt = 0; mt < 4; mt++) {
#pragma unroll
                        for (int j = 0; j < 4; j++) {
                            uint32_t b0 = bf[j >> 1][(j & 1) * 2];
                            uint32_t b1 = bf[j >> 1][(j & 1) * 2 + 1];
                            mma16816(acc[mt][j], a_f[mt], b0, b1);
                        }
                    }
                }
            }
        }

        // epilogue: bias + leaky, store fp16
#pragma unroll
        for (int mt = 0; mt < 4; mt++) {
            int oy = oy0 + wm * 4 + mt;
            if (oy >= Sout) continue;
#pragma unroll
            for (int rs = 0; rs < 2; rs++) {
                int c = (lane >> 2) + rs * 8;
                int ox = ox0 + c;
                if (ox >= Sout) continue;
                size_t pix = (size_t)oy * Sout + ox;
                size_t eoff = ((size_t)b * Spo + pix) * 64 + wn * 32 + (lane & 3) * 2;
#pragma unroll
                for (int j = 0; j < 4; j++) {
                    float v0 = acc[mt][j][rs * 2 + 0] + bv[j * 2 + 0];
                    float v1 = acc[mt][j][rs * 2 + 1] + bv[j * 2 + 1];
                    v0 = v0 > 0.f ? v0 : 0.02f * v0;
                    v1 = v1 > 0.f ? v1 : 0.02f * v1;
                    __half h0 = __float2half_rn(v0);
                    __half h1 = __float2half_rn(v1);
                    unsigned ph = (unsigned)__half_as_ushort(h0) | ((unsigned)__half_as_ushort(h1) << 16);
                    *(unsigned*)(out_a + eoff + j * 8) = ph;
                }
            }
        }
        s ^= 1;
    }
}

// ---------------- tail (mma, N=8 padded from 3, tanh epilogue) ---------------
__global__ __launch_bounds__(NTT, 2)
void tail_mma_kernel(const __half* __restrict__ in_a,
                     const float* __restrict__ bias,    // [16][3]
                     float* __restrict__ out, float cb)
{
    extern __shared__ __align__(1024) char smem[];
    const int Sin = 258, Sout = 256;
    const int b = blockIdx.z, slot = blockIdx.x, nslots = gridDim.x;
    const int tid = threadIdx.x, wid = tid >> 5, lane = tid & 31;
    uint32_t sbase = smem_u32(smem);
    const uint32_t A[2] = { sbase + TSM_A0, sbase + TSM_A1 };

    // stage tail weights: [tap][ic 64][oc8] fp16, 16B rows
    {
        const __half* wb = g_twt + (size_t)b * 9 * 512;
        for (int i = tid; i < 576; i += NTT) {
            *(uint4*)(smem + TSM_WS + i * 16) = *((const uint4*)wb + i);
        }
    }

    const __half* ia = in_a + (size_t)b * Sin * Sin * 64;
    const int nct = 16, ntiles = 32 * 16;    // 8x16 px tiles over 256x256

    const int laneA = (lane & 15) * 128 + (lane >> 4) * 16;

    int s = 0;
    {
        int t0 = slot;
        if (t0 < ntiles) {
            int rt = t0 / nct, ct = t0 - rt * nct;
            gather10(A[0], ia, rt * 8, ct * 16, Sin, tid);
        } else {
            CP_COMMIT();
        }
    }

    for (int tt = slot; tt < ntiles; tt += nslots) {
        int rt = tt / nct, ct = tt - rt * nct;
        int oy0 = rt * 8, ox0 = ct * 16;

        __syncthreads();
        int tn = tt + nslots;
        if (tn < ntiles) {
            int rtn = tn / nct, ctn = tn - rtn * nct;
            gather10(A[s ^ 1], ia, rtn * 8, ctn * 16, Sin, tid);
        } else {
            CP_COMMIT();
        }
        CP_WAIT(1); __syncthreads();

        float acc[4] = {0.f, 0.f, 0.f, 0.f};

#pragma unroll
        for (int ky = 0; ky < 3; ky++) {
#pragma unroll
            for (int kx = 0; kx < 3; kx++) {
                uint32_t wtap = sbase + TSM_WS + (ky * 3 + kx) * 1024;
#pragma unroll
                for (int kh = 0; kh < 2; kh++) {
                    uint32_t bf[4];
                    ldsm4t(bf, wtap + kh * 512 + lane * 16);
#pragma unroll
                    for (int wh = 0; wh < 2; wh++) {
                        int kc = kh * 2 + wh;
                        int ebase = ((wid + ky) * 18 + kx) * 128 + kc * 32;
                        uint32_t a_f[4];
                        ldsm4(a_f, A[s] + swz((uint32_t)(ebase + laneA)));
                        mma16816(acc, a_f, bf[wh * 2], bf[wh * 2 + 1]);
                    }
                }
            }
        }

        // epilogue: tanh(acc + bias)
        {
            int oy = oy0 + wid;
            int oc0 = (lane & 3) * 2;
            if (oc0 < 3) {
                int p0 = lane >> 2;
#pragma unroll
                for (int rs = 0; rs < 2; rs++) {
                    int ox = ox0 + p0 + rs * 8;
                    float v0 = acc[rs * 2 + 0] + bias[b * 3 + oc0] * cb;
                    out[((size_t)(b * 3 + oc0) * Sout + oy) * Sout + ox] = tanhf(v0);
                    if (oc0 + 1 < 3) {
                        float v1 = acc[rs * 2 + 1] + bias[b * 3 + oc0 + 1] * cb;
                        out[((size_t)(b * 3 + oc0 + 1) * Sout + oy) * Sout + ox] = tanhf(v1);
                    }
                }
            }
        }
        s ^= 1;
    }
}

// ---------------- launch ----------------
extern "C" void kernel_launch(void* const* d_in, const int* in_sizes, int n_in,
                              void* d_out, int out_size)
{
    const float* noise  = (const float*)d_in[0];
    const float* head_w = (const float*)d_in[1];
    const float* head_b = (const float*)d_in[2];
    const float* body_w = (const float*)d_in[3];
    const float* body_b = (const float*)d_in[4];
    const float* tail_w = (const float*)d_in[5];
    const float* tail_b = (const float*)d_in[6];
    float* out = (float*)d_out;

    __half *actA, *actB, *wt;
    cudaGetSymbolAddress((void**)&actA, g_actA);
    cudaGetSymbolAddress((void**)&actB, g_actB);
    cudaGetSymbolAddress((void**)&wt, g_wt);

    cudaFuncSetAttribute(body_mma_kernel, cudaFuncAttributeMaxDynamicSharedMemorySize, SMEM_BODY);
    cudaFuncSetAttribute(tail_mma_kernel, cudaFuncAttributeMaxDynamicSharedMemorySize, SMEM_TAIL);

    const double lr_gain = sqrt(2.0 / (1.0 + 0.02 * 0.02));
    const float cw_head = (float)(lr_gain / sqrt(27.0));
    const float cb_head = (float)(1.0 / sqrt(3.0));
    const float cw_body = (float)(lr_gain / 24.0);
    const float cb_body = 0.125f;
    const float cw_tail = (float)((5.0 / 3.0) / 24.0);
    const float cb_tail = 0.125f;

    // weight preps (fold cw, fp16, k-major)
    {
        int N = 5 * 16 * 9 * 64 * 64;
        prep_kernel<<<(N + 255) / 256, 256>>>(body_w, cw_body);
        int M = 16 * 9 * 64 * 8;
        prep_tail_kernel<<<(M + 255) / 256, 256>>>(tail_w, cw_tail);
    }

    // head -> actA (268), 64 oc per block
    {
        dim3 grid((268 + 31) / 32, (268 + 7) / 8, BATCH);
        head_kernel<<<grid, 256>>>(noise, head_w, head_b, actA, cw_head, cb_head);
    }

    // 5 body layers, ping-pong
    __half *src = actA, *dst = actB;
    int Sin = 268;
    for (int l = 0; l < 5; l++) {
        dim3 grid(9, 1, BATCH);
        const __half* wt_l = wt + (size_t)l * 16 * 9 * 4096;
        const float* bias_l = body_b + (size_t)l * 16 * 64;
        body_mma_kernel<<<grid, NTB, SMEM_BODY>>>(src, wt_l, bias_l, dst, Sin, cb_body);
        __half* t = src; src = dst; dst = t;
        Sin -= 2;
    }

    // tail (tensorized): src 258 -> out 256
    {
        dim3 grid(36, 1, BATCH);
        tail_mma_kernel<<<grid, NTT, SMEM_TAIL>>>(src, tail_b, out, cb_tail);
    }
}

// round 13
// speedup vs baseline: 1.2067x; 1.2067x over previous
#include <cuda_runtime.h>
#include <cuda_fp16.h>
#include <math.h>
#include <stdint.h>

#define BATCH 16
#define MAXPIX (268u * 268u)

// activations NHWC fp16 (single precision-term), ping-pong
__device__ __half g_actA[16u * MAXPIX * 64u];
__device__ __half g_actB[16u * MAXPIX * 64u];
// fp16 body weights, K-MAJOR: [5][16][tap 9][ic 64][oc 64]
__device__ __half g_wt[5u * 16u * 9u * 64u * 64u];
// fp16 tail weights: [16][tap 9][ic 64][oc 8(pad)]
__device__ __half g_twt[16u * 9u * 64u * 8u];

// ---------------- helpers ----------------
__device__ __forceinline__ uint32_t smem_u32(const void* p) {
    uint32_t a;
    asm("{ .reg .u64 t; cvta.to.shared.u64 t, %1; cvt.u32.u64 %0, t; }" : "=r"(a) : "l"(p));
    return a;
}
__device__ __forceinline__ uint32_t swz(uint32_t o) { return o ^ ((o >> 3) & 0x70); }

__device__ __forceinline__ void ldsm4(uint32_t r[4], uint32_t addr) {
    asm volatile("ldmatrix.sync.aligned.m8n8.x4.shared.b16 {%0,%1,%2,%3}, [%4];"
        : "=r"(r[0]), "=r"(r[1]), "=r"(r[2]), "=r"(r[3]) : "r"(addr));
}
__device__ __forceinline__ void ldsm4t(uint32_t r[4], uint32_t addr) {
    asm volatile("ldmatrix.sync.aligned.m8n8.x4.trans.shared.b16 {%0,%1,%2,%3}, [%4];"
        : "=r"(r[0]), "=r"(r[1]), "=r"(r[2]), "=r"(r[3]) : "r"(addr));
}
__device__ __forceinline__ void mma16816(float d[4], const uint32_t a[4], uint32_t b0, uint32_t b1) {
    asm volatile("mma.sync.aligned.m16n8k16.row.col.f32.f16.f16.f32 "
        "{%0,%1,%2,%3}, {%4,%5,%6,%7}, {%8,%9}, {%0,%1,%2,%3};"
        : "+f"(d[0]), "+f"(d[1]), "+f"(d[2]), "+f"(d[3])
        : "r"(a[0]), "r"(a[1]), "r"(a[2]), "r"(a[3]), "r"(b0), "r"(b1));
}
__device__ __forceinline__ void cp16(uint32_t dst, const void* src) {
    asm volatile("cp.async.cg.shared.global [%0], [%1], 16;" :: "r"(dst), "l"(src) : "memory");
}
#define CP_COMMIT() asm volatile("cp.async.commit_group;" ::: "memory")
#define CP_WAIT(n)  asm volatile("cp.async.wait_group %0;" :: "n"(n) : "memory")

// smem layout for body kernel (8x16 px tile -> 10x18 slab)
#define SM_WS   0          // 9 x 8192 = 73728
#define SM_A0   73728
#define SM_A1   97280
#define SMEM_BODY 120832

// smem layout for tail kernel (8x16 px tile, 10x18 slab)
#define TSM_WS  0          // 9 x 1024 = 9216
#define TSM_A0  9216
#define TSM_A1  32768
#define SMEM_TAIL 56320

#define NTHR 256

// ---------------- weight prep: [l][b][tap][ic][oc], cw folded, fp16 ----------
__global__ void prep_kernel(const float* __restrict__ bw, float cw) {
    int idx = blockIdx.x * blockDim.x + threadIdx.x;
    const int N = 5 * 16 * 9 * 64 * 64;
    if (idx >= N) return;
    int oc = idx & 63;
    int ic = (idx >> 6) & 63;
    int tap = (idx >> 12) % 9;
    int rest = idx / (9 * 64 * 64);   // l*16+b
    float v = bw[(((size_t)rest * 64 + oc) * 64 + ic) * 9 + tap] * cw;
    g_wt[idx] = __float2half_rn(v);
}

// tail weights: [b][tap][ic][oc8], cw folded, oc>=3 zero
__global__ void prep_tail_kernel(const float* __restrict__ tw, float cw) {
    int idx = blockIdx.x * blockDim.x + threadIdx.x;
    const int N = 16 * 9 * 64 * 8;
    if (idx >= N) return;
    int oc = idx & 7;
    int ic = (idx >> 3) & 63;
    int tap = (idx >> 9) % 9;
    int b = idx / (9 * 64 * 8);
    float v = 0.f;
    if (oc < 3) v = tw[(((size_t)b * 3 + oc) * 64 + ic) * 9 + tap] * cw;
    g_twt[idx] = __float2half_rn(v);
}

// ---------------- head (scalar fp32, writes NHWC fp16) ----------------
__global__ __launch_bounds__(256)
void head_kernel(const float* __restrict__ noise, const float* __restrict__ hw,
                 const float* __restrict__ hb, __half* __restrict__ oh,
                 float cw, float cb)
{
    const int Sout = 268;
    int b = blockIdx.z >> 2;
    int oc0 = (blockIdx.z & 3) << 4;
    int tx0 = blockIdx.x * 32, ty0 = blockIdx.y * 8;
    int tid = threadIdx.x, tx = tid & 31, ty = tid >> 5;

    __shared__ __align__(16) float ws[3 * 9 * 16];
    __shared__ float xs[3 * 10 * 34];

    for (int i = tid; i < 3 * 144; i += 256) {
        int oc = i & 15, k = (i >> 4) % 9, ic = i / 144;
        ws[i] = hw[((b * 64 + oc0 + oc) * 3 + ic) * 9 + k];
    }
    for (int i = tid; i < 3 * 340; i += 256) {
        int ic = i / 340, rem = i % 340, r = rem / 34, c = rem % 34;
        int gy = ty0 + r - 7, gx = tx0 + c - 7;
        float v = 0.f;
        if (gy >= 0 && gy < 256 && gx >= 0 && gx < 256)
            v = noise[((size_t)(b * 3 + ic) * 256 + gy) * 256 + gx];
        xs[i] = v;
    }
    __syncthreads();

    float acc[16];
#pragma unroll
    for (int o = 0; o < 16; o++) acc[o] = 0.f;
#pragma unroll
    for (int ic = 0; ic < 3; ic++) {
        const float* xp = xs + ic * 340 + ty * 34 + tx;
        float xv[9];
#pragma unroll
        for (int ky = 0; ky < 3; ky++)
#pragma unroll
            for (int kx = 0; kx < 3; kx++) xv[ky * 3 + kx] = xp[ky * 34 + kx];
        const float4* wp = (const float4*)(ws + ic * 144);
#pragma unroll
        for (int k = 0; k < 9; k++) {
#pragma unroll
            for (int q = 0; q < 4; q++) {
                float4 w4 = wp[k * 4 + q];
                acc[q * 4 + 0] = fmaf(xv[k], w4.x, acc[q * 4 + 0]);
                acc[q * 4 + 1] = fmaf(xv[k], w4.y, acc[q * 4 + 1]);
                acc[q * 4 + 2] = fmaf(xv[k], w4.z, acc[q * 4 + 2]);
                acc[q * 4 + 3] = fmaf(xv[k], w4.w, acc[q * 4 + 3]);
            }
        }
    }

    int ox = tx0 + tx, oy = ty0 + ty;
    if (ox < Sout && oy < Sout) {
        __align__(16) __half h16[16];
#pragma unroll
        for (int o = 0; o < 16; o++) {
            float v = acc[o] * cw + hb[b * 64 + oc0 + o] * cb;
            v = v > 0.f ? v : 0.02f * v;
            h16[o] = __float2half_rn(v);
        }
        size_t obase = ((size_t)b * (Sout * Sout) + (size_t)oy * Sout + ox) * 64 + oc0;
        uint4* dh = (uint4*)(oh + obase);
        dh[0] = ((uint4*)h16)[0]; dh[1] = ((uint4*)h16)[1];
    }
}

// ---------------- A-slab gather via cp.async (10x18 slab) --------------------
__device__ __forceinline__ void gather_tile(uint32_t dst,
                                            const __half* __restrict__ src,
                                            int oy0, int ox0, int Sin, int tid)
{
    for (int i = tid; i < 1440; i += NTHR) {
        int e = i >> 3, q = i & 7;
        int er = e / 18, ec = e - er * 18;
        int iy = oy0 + er; if (iy > Sin - 1) iy = Sin - 1;
        int ix = ox0 + ec; if (ix > Sin - 1) ix = Sin - 1;
        size_t base = ((size_t)iy * Sin + ix) * 64 + q * 8;
        cp16(dst + swz((uint32_t)(e * 128 + q * 16)), src + base);
    }
    CP_COMMIT();
}

// ---------------- body (mma.sync fp16, frag double-buffered) ----------------
__global__ __launch_bounds__(NTHR, 1)
void body_mma_kernel(const __half* __restrict__ in_a,
                     const __half* __restrict__ wt,     // [16][9][64 ic][64 oc]
                     const float* __restrict__ bias,    // [16][64]
                     __half* __restrict__ out_a,
                     int Sin, float cb)
{
    extern __shared__ __align__(1024) char smem[];
    const int Sout = Sin - 2;
    const int b = blockIdx.z, slot = blockIdx.x;
    const int tid = threadIdx.x, wid = tid >> 5, lane = tid & 31;
    const int wm = wid & 3, wn = wid >> 2;       // 4 x 2 warp grid, M32 x N32
    uint32_t sbase = smem_u32(smem);
    const uint32_t A[2] = { sbase + SM_A0, sbase + SM_A1 };

    // stage weights: [tap][ic 64][128B oc], SW128-swizzled
    {
        const __half* wb = wt + (size_t)b * 9 * 4096;
        for (int i = tid; i < 4608; i += NTHR) {
            int j = i & 511, tap = i >> 9;
            int ic = j >> 3, q = j & 7;
            const uint4* src = (const uint4*)(wb + ((size_t)tap * 64 + ic) * 64) + q;
            *(uint4*)(smem + SM_WS + tap * 8192 + swz(ic * 128 + q * 16)) = *src;
        }
    }

    float bv[8];
#pragma unroll
    for (int j = 0; j < 4; j++) {
        int oc = wn * 32 + j * 8 + (lane & 3) * 2;
        bv[j * 2 + 0] = bias[b * 64 + oc] * cb;
        bv[j * 2 + 1] = bias[b * 64 + oc + 1] * cb;
    }

    const __half* ia = in_a + (size_t)b * Sin * Sin * 64;
    const int nrt = (Sout + 7) >> 3, nct = (Sout + 15) >> 4;
    const int ntiles = nrt * nct;
    const size_t Spo = (size_t)Sout * Sout;

    const int laneA = (lane & 15) * 128 + (lane >> 4) * 16;
    const int laneB = (lane & 15) * 128 + (lane >> 4) * 16 + wn * 64;

    int s = 0;
    {
        int t0 = slot;
        if (t0 < ntiles) {
            int rt = t0 / nct, ct = t0 - rt * nct;
            gather_tile(A[0], ia, rt * 8, ct * 16, Sin, tid);
        } else {
            CP_COMMIT();
        }
    }

    for (int tt = slot; tt < ntiles; tt += 9) {
        int rt = tt / nct, ct = tt - rt * nct;
        int oy0 = rt * 8, ox0 = ct * 16;

        __syncthreads();
        int tn = tt + 9;
        if (tn < ntiles) {
            int rtn = tn / nct, ctn = tn - rtn * nct;
            gather_tile(A[s ^ 1], ia, rtn * 8, ctn * 16, Sin, tid);
        } else {
            CP_COMMIT();
        }
        CP_WAIT(1); __syncthreads();

        float acc[2][4][4];
#pragma unroll
        for (int mt = 0; mt < 2; mt++)
#pragma unroll
            for (int j = 0; j < 4; j++)
#pragma unroll
                for (int r = 0; r < 4; r++) acc[mt][j][r] = 0.f;

        // fragment double-buffers (parity-indexed)
        uint32_t a_f[2][2][4], bf[2][2][4];

        // preload it = 0 (tap 0: ky=0,kx=0, kc=0)
#pragma unroll
        for (int mt = 0; mt < 2; mt++) {
            int ebase = ((wm * 2 + mt) * 18) * 128;
            ldsm4(a_f[0][mt], A[s] + swz((uint32_t)(ebase + laneA)));
        }
#pragma unroll
        for (int nt = 0; nt < 2; nt++)
            ldsm4t(bf[0][nt], sbase + SM_WS + swz((uint32_t)(laneB + nt * 32)));

        // 36 steps = 9 taps x 4 kc, prefetch next step's frags before MMAs
#pragma unroll
        for (int it = 0; it < 36; it++) {
            const int p = it & 1;
            if (it < 35) {
                const int itn = it + 1;
                const int tapn = itn >> 2, kcn = itn & 3;
                const int kyn = tapn / 3, kxn = tapn % 3;
                uint32_t wtile = sbase + SM_WS + tapn * 8192;
#pragma unroll
                for (int mt = 0; mt < 2; mt++) {
                    int ebase = ((wm * 2 + mt + kyn) * 18 + kxn) * 128 + kcn * 32;
                    ldsm4(a_f[p ^ 1][mt], A[s] + swz((uint32_t)(ebase + laneA)));
                }
#pragma unroll
                for (int nt = 0; nt < 2; nt++)
                    ldsm4t(bf[p ^ 1][nt], wtile + swz((uint32_t)(kcn * 2048 + laneB + nt * 32)));
            }
#pragma unroll
            for (int mt = 0; mt < 2; mt++) {
#pragma unroll
                for (int j = 0; j < 4; j++) {
                    uint32_t b0 = bf[p][j >> 1][(j & 1) * 2];
                    uint32_t b1 = bf[p][j >> 1][(j & 1) * 2 + 1];
                    mma16816(acc[mt][j], a_f[p][mt], b0, b1);
                }
            }
        }

        // epilogue: bias + leaky, store fp16
#pragma unroll
        for (int mt = 0; mt < 2; mt++) {
            int oy = oy0 + wm * 2 + mt;
            if (oy >= Sout) continue;
#pragma unroll
            for (int rs = 0; rs < 2; rs++) {
                int c = (lane >> 2) + rs * 8;
                int ox = ox0 + c;
                if (ox >= Sout) continue;
                size_t pix = (size_t)oy * Sout + ox;
                size_t eoff = ((size_t)b * Spo + pix) * 64 + wn * 32 + (lane & 3) * 2;
#pragma unroll
                for (int j = 0; j < 4; j++) {
                    float v0 = acc[mt][j][rs * 2 + 0] + bv[j * 2 + 0];
                    float v1 = acc[mt][j][rs * 2 + 1] + bv[j * 2 + 1];
                    v0 = v0 > 0.f ? v0 : 0.02f * v0;
                    v1 = v1 > 0.f ? v1 : 0.02f * v1;
                    __half h0 = __float2half_rn(v0);
                    __half h1 = __float2half_rn(v1);
                    unsigned ph = (unsigned)__half_as_ushort(h0) | ((unsigned)__half_as_ushort(h1) << 16);
                    *(unsigned*)(out_a + eoff + j * 8) = ph;
                }
            }
        }
        s ^= 1;
    }
}

// ---------------- tail (mma, N=8 padded from 3, tanh epilogue) ---------------
__global__ __launch_bounds__(NTHR, 2)
void tail_mma_kernel(const __half* __restrict__ in_a,
                     const float* __restrict__ bias,    // [16][3]
                     float* __restrict__ out, float cb)
{
    extern __shared__ __align__(1024) char smem[];
    const int Sin = 258, Sout = 256;
    const int b = blockIdx.z, slot = blockIdx.x, nslots = gridDim.x;
    const int tid = threadIdx.x, wid = tid >> 5, lane = tid & 31;
    uint32_t sbase = smem_u32(smem);
    const uint32_t A[2] = { sbase + TSM_A0, sbase + TSM_A1 };

    // stage tail weights: [tap][ic 64][oc8] fp16, 16B rows
    {
        const __half* wb = g_twt + (size_t)b * 9 * 512;
        for (int i = tid; i < 576; i += NTHR) {
            *(uint4*)(smem + TSM_WS + i * 16) = *((const uint4*)wb + i);
        }
    }

    const __half* ia = in_a + (size_t)b * Sin * Sin * 64;
    const int nct = 16, ntiles = 32 * 16;    // 8x16 px tiles over 256x256

    const int laneA = (lane & 15) * 128 + (lane >> 4) * 16;

    int s = 0;
    {
        int t0 = slot;
        if (t0 < ntiles) {
            int rt = t0 / nct, ct = t0 - rt * nct;
            gather_tile(A[0], ia, rt * 8, ct * 16, Sin, tid);
        } else {
            CP_COMMIT();
        }
    }

    for (int tt = slot; tt < ntiles; tt += nslots) {
        int rt = tt / nct, ct = tt - rt * nct;
        int oy0 = rt * 8, ox0 = ct * 16;

        __syncthreads();
        int tn = tt + nslots;
        if (tn < ntiles) {
            int rtn = tn / nct, ctn = tn - rtn * nct;
            gather_tile(A[s ^ 1], ia, rtn * 8, ctn * 16, Sin, tid);
        } else {
            CP_COMMIT();
        }
        CP_WAIT(1); __syncthreads();

        float acc[4] = {0.f, 0.f, 0.f, 0.f};

#pragma unroll
        for (int ky = 0; ky < 3; ky++) {
#pragma unroll
            for (int kx = 0; kx < 3; kx++) {
                uint32_t wtap = sbase + TSM_WS + (ky * 3 + kx) * 1024;
#pragma unroll
                for (int kh = 0; kh < 2; kh++) {
                    uint32_t bf[4];
                    ldsm4t(bf, wtap + kh * 512 + lane * 16);
#pragma unroll
                    for (int wh = 0; wh < 2; wh++) {
                        int kc = kh * 2 + wh;
                        int ebase = ((wid + ky) * 18 + kx) * 128 + kc * 32;
                        uint32_t a_f[4];
                        ldsm4(a_f, A[s] + swz((uint32_t)(ebase + laneA)));
                        mma16816(acc, a_f, bf[wh * 2], bf[wh * 2 + 1]);
                    }
                }
            }
        }

        // epilogue: tanh(acc + bias)
        {
            int oy = oy0 + wid;
            int oc0 = (lane & 3) * 2;
            if (oc0 < 3) {
                int p0 = lane >> 2;
#pragma unroll
                for (int rs = 0; rs < 2; rs++) {
                    int ox = ox0 + p0 + rs * 8;
                    float v0 = acc[rs * 2 + 0] + bias[b * 3 + oc0] * cb;
                    out[((size_t)(b * 3 + oc0) * Sout + oy) * Sout + ox] = tanhf(v0);
                    if (oc0 + 1 < 3) {
                        float v1 = acc[rs * 2 + 1] + bias[b * 3 + oc0 + 1] * cb;
                        out[((size_t)(b * 3 + oc0 + 1) * Sout + oy) * Sout + ox] = tanhf(v1);
                    }
                }
            }
        }
        s ^= 1;
    }
}

// ---------------- launch ----------------
extern "C" void kernel_launch(void* const* d_in, const int* in_sizes, int n_in,
                              void* d_out, int out_size)
{
    const float* noise  = (const float*)d_in[0];
    const float* head_w = (const float*)d_in[1];
    const float* head_b = (const float*)d_in[2];
    const float* body_w = (const float*)d_in[3];
    const float* body_b = (const float*)d_in[4];
    const float* tail_w = (const float*)d_in[5];
    const float* tail_b = (const float*)d_in[6];
    float* out = (float*)d_out;

    __half *actA, *actB, *wt;
    cudaGetSymbolAddress((void**)&actA, g_actA);
    cudaGetSymbolAddress((void**)&actB, g_actB);
    cudaGetSymbolAddress((void**)&wt, g_wt);

    cudaFuncSetAttribute(body_mma_kernel, cudaFuncAttributeMaxDynamicSharedMemorySize, SMEM_BODY);
    cudaFuncSetAttribute(tail_mma_kernel, cudaFuncAttributeMaxDynamicSharedMemorySize, SMEM_TAIL);

    const double lr_gain = sqrt(2.0 / (1.0 + 0.02 * 0.02));
    const float cw_head = (float)(lr_gain / sqrt(27.0));
    const float cb_head = (float)(1.0 / sqrt(3.0));
    const float cw_body = (float)(lr_gain / 24.0);
    const float cb_body = 0.125f;
    const float cw_tail = (float)((5.0 / 3.0) / 24.0);
    const float cb_tail = 0.125f;

    // weight preps (fold cw, fp16, k-major)
    {
        int N = 5 * 16 * 9 * 64 * 64;
        prep_kernel<<<(N + 255) / 256, 256>>>(body_w, cw_body);
        int M = 16 * 9 * 64 * 8;
        prep_tail_kernel<<<(M + 255) / 256, 256>>>(tail_w, cw_tail);
    }

    // head -> actA (268)
    {
        dim3 grid((268 + 31) / 32, (268 + 7) / 8, BATCH * 4);
        head_kernel<<<grid, 256>>>(noise, head_w, head_b, actA, cw_head, cb_head);
    }

    // 5 body layers, ping-pong
    __half *src = actA, *dst = actB;
    int Sin = 268;
    for (int l = 0; l < 5; l++) {
        dim3 grid(9, 1, BATCH);
        const __half* wt_l = wt + (size_t)l * 16 * 9 * 4096;
        const float* bias_l = body_b + (size_t)l * 16 * 64;
        body_mma_kernel<<<grid, NTHR, SMEM_BODY>>>(src, wt_l, bias_l, dst, Sin, cb_body);
        __half* t = src; src = dst; dst = t;
        Sin -= 2;
    }

    // tail (tensorized): src 258 -> out 256
    {
        dim3 grid(36, 1, BATCH);
        tail_mma_kernel<<<grid, NTHR, SMEM_TAIL>>>(src, tail_b, out, cb_tail);
    }
}